// round 14
// baseline (speedup 1.0000x reference)
#include <cuda_runtime.h>
#include <cstdint>

#define NN 50000
#define NE 800000
#define DD 64
#define CSR_GRID 296   // 2 blocks/SM guaranteed co-resident (spin-wait safe)

// ---------------- device scratch (no allocation allowed) ----------------
// g_cnt / g_done / g_done2 / g_flag are zero at module load and restored to
// zero by the end of every kernel_launch call.
__device__ int   g_cnt[NN];
__device__ int   g_done;
__device__ int   g_done2;
__device__ int   g_flag;
__device__ int   g_rowptr[NN + 1];
__device__ int   g_rank[NE];      // per-edge rank within its dst group
__device__ int2  g_pair[NE];      // {src node id, original edge id}, dst-grouped
__device__ float g_hneigh[(size_t)NN * 128];
__device__ float g_hn1[(size_t)NN * DD];
__device__ float g_P[(size_t)NN * DD];
__device__ float g_Q[(size_t)NN * DD];

// ---------------- f32x2 packed-FMA helpers (sm_100+) ----------------
static __device__ __forceinline__ unsigned long long pack2(float a, float b) {
    unsigned long long r;
    asm("mov.b64 %0, {%1, %2};" : "=l"(r) : "f"(a), "f"(b));
    return r;
}
static __device__ __forceinline__ float2 unpack2(unsigned long long v) {
    float2 f;
    asm("mov.b64 {%0, %1}, %2;" : "=f"(f.x), "=f"(f.y) : "l"(v));
    return f;
}
static __device__ __forceinline__ void fma2(unsigned long long& d,
                                            unsigned long long a,
                                            unsigned long long b) {
    asm("fma.rn.f32x2 %0, %1, %2, %0;" : "+l"(d) : "l"(a), "l"(b));
}

static __device__ __forceinline__ float4 relu_add(float4 x, float4 q) {
    return make_float4(fmaxf(x.x + q.x, 0.f), fmaxf(x.y + q.y, 0.f),
                       fmaxf(x.z + q.z, 0.f), fmaxf(x.w + q.w, 0.f));
}
static __device__ __forceinline__ void acc4(float4& a, float4 x) {
    a.x += x.x; a.y += x.y; a.z += x.z; a.w += x.w;
}

// 16 independent f32x2 rank-1 updates: 4 nodes x 8 cols
static __device__ __forceinline__ void tile_fma(unsigned long long* acc,
                                                float4 xv,
                                                ulonglong2 wA, ulonglong2 wB) {
    unsigned long long x0 = pack2(xv.x, xv.x), x1 = pack2(xv.y, xv.y),
                       x2 = pack2(xv.z, xv.z), x3 = pack2(xv.w, xv.w);
    fma2(acc[0],  x0, wA.x); fma2(acc[1],  x0, wA.y);
    fma2(acc[2],  x0, wB.x); fma2(acc[3],  x0, wB.y);
    fma2(acc[4],  x1, wA.x); fma2(acc[5],  x1, wA.y);
    fma2(acc[6],  x1, wB.x); fma2(acc[7],  x1, wB.y);
    fma2(acc[8],  x2, wA.x); fma2(acc[9],  x2, wA.y);
    fma2(acc[10], x2, wB.x); fma2(acc[11], x2, wB.y);
    fma2(acc[12], x3, wA.x); fma2(acc[13], x3, wA.y);
    fma2(acc[14], x3, wB.x); fma2(acc[15], x3, wB.y);
}

// -------- persistent CSR build: count + rank -> scan -> fill, ONE kernel ----
// grid = CSR_GRID (co-resident), so the post-scan flag spin is deadlock-free.
__global__ __launch_bounds__(256) void k_csr(const int* __restrict__ src,
                                             const int* __restrict__ dst) {
    const int tid = threadIdx.x;
    const int ITEMS = NE / 4;
    const int stride = CSR_GRID * 256;

    // ---- phase 1: count + per-edge rank (int4-vectorized) ----
    for (int i = blockIdx.x * 256 + tid; i < ITEMS; i += stride) {
        int4 d4 = __ldg((const int4*)dst + i);
        int4 r4;
        r4.x = atomicAdd(&g_cnt[d4.x], 1);
        r4.y = atomicAdd(&g_cnt[d4.y], 1);
        r4.z = atomicAdd(&g_cnt[d4.z], 1);
        r4.w = atomicAdd(&g_cnt[d4.w], 1);
        ((int4*)g_rank)[i] = r4;
    }
    __threadfence();
    __syncthreads();

    __shared__ int s_last;
    if (tid == 0) s_last = (atomicAdd(&g_done, 1) == CSR_GRID - 1);
    __syncthreads();

    // ---- phase 2: last block scans, then releases everyone ----
    if (s_last) {
        __threadfence();
        __shared__ int part[256];
        const int C = (NN + 255) / 256;
        int beg = tid * C;
        int end = min(beg + C, NN);
        int s = 0;
        for (int j = beg; j < end; j++) s += g_cnt[j];
        part[tid] = s;
        __syncthreads();
        for (int off = 1; off < 256; off <<= 1) {
            int add = (tid >= off) ? part[tid - off] : 0;
            __syncthreads();
            part[tid] += add;
            __syncthreads();
        }
        int run = (tid == 0) ? 0 : part[tid - 1];
        for (int j = beg; j < end; j++) { g_rowptr[j] = run; run += g_cnt[j]; }
        if (tid == 255) g_rowptr[NN] = part[255];
        __threadfence();
        __syncthreads();
        if (tid == 0) atomicExch(&g_flag, 1);
    }

    // ---- all blocks wait for the scan ----
    if (tid == 0) {
        while (atomicAdd(&g_flag, 0) == 0) __nanosleep(64);
    }
    __syncthreads();

    // ---- phase 3: atomic-free fill (position = rowptr[dst] + rank) ----
    for (int i = blockIdx.x * 256 + tid; i < ITEMS; i += stride) {
        int4 d4 = __ldg((const int4*)dst + i);
        int4 s4 = __ldg((const int4*)src + i);
        int4 r4 = ((const int4*)g_rank)[i];
        int e = i * 4;
        g_pair[__ldg(g_rowptr + d4.x) + r4.x] = make_int2(s4.x, e);
        g_pair[__ldg(g_rowptr + d4.y) + r4.y] = make_int2(s4.y, e + 1);
        g_pair[__ldg(g_rowptr + d4.z) + r4.z] = make_int2(s4.z, e + 2);
        g_pair[__ldg(g_rowptr + d4.w) + r4.w] = make_int2(s4.w, e + 3);
    }

    // ---- reset control words for the next kernel_launch call ----
    __threadfence();
    __syncthreads();
    if (tid == 0 && atomicAdd(&g_done2, 1) == CSR_GRID - 1) {
        g_done = 0; g_done2 = 0; g_flag = 0;
    }
}

// ---------------- aggregation: one warp per node, mean of [h[src] | h_e] ----
template <int LAYER>
static __device__ __forceinline__ float4 gat(const float* __restrict__ tb,
                                             int s, int c, int half) {
    const float4* p = (const float4*)(tb + (size_t)s * 64 + c);
    if (LAYER == 0) return half ? __ldcs(p) : __ldg(p);
    return __ldg(p);
}

template <int LAYER>
__global__ __launch_bounds__(256) void k_agg(const float* __restrict__ hn,
                                             const float* __restrict__ ef,
                                             const float* __restrict__ P0,
                                             const float* __restrict__ Q0,
                                             const float* __restrict__ be0) {
    int w = (blockIdx.x * 256 + threadIdx.x) >> 5;
    if (w >= NN) return;
    const int lane = threadIdx.x & 31;
    const int half = lane >> 4;
    const int t = lane & 15;
    const int c = t << 2;
    const int base = half << 4;
    const int b = g_rowptr[w];
    const int e = g_rowptr[w + 1];

    const float* tb = half ? (LAYER ? P0 : ef) : hn;

    float4 qb = make_float4(0.f, 0.f, 0.f, 0.f);
    if (LAYER && half) {
        float4 q  = *(const float4*)(Q0 + (size_t)w * 64 + c);
        float4 bb = *(const float4*)(be0 + c);
        qb = make_float4(q.x + bb.x, q.y + bb.y, q.z + bb.z, q.w + bb.w);
    }

    float4 acc = make_float4(0.f, 0.f, 0.f, 0.f);

    int2 pr = make_int2(0, 0);
    if (b + t < e) pr = __ldg(g_pair + b + t);

#define GATHER(s) gat<LAYER>(tb, (s), c, half)
    for (int j0 = b; j0 < e; j0 += 16) {
        int m = e - j0;
        if (m > 16) m = 16;
        int idx = (LAYER == 0 && half) ? pr.y : pr.x;
        int2 prn = make_int2(0, 0);
        int j1 = j0 + 16;
        if (j1 + t < e) prn = __ldg(g_pair + j1 + t);

        int k = 0;
        for (; k + 8 <= m; k += 8) {
            int s0 = __shfl_sync(0xffffffffu, idx, base + k);
            int s1 = __shfl_sync(0xffffffffu, idx, base + k + 1);
            int s2 = __shfl_sync(0xffffffffu, idx, base + k + 2);
            int s3 = __shfl_sync(0xffffffffu, idx, base + k + 3);
            int s4 = __shfl_sync(0xffffffffu, idx, base + k + 4);
            int s5 = __shfl_sync(0xffffffffu, idx, base + k + 5);
            int s6 = __shfl_sync(0xffffffffu, idx, base + k + 6);
            int s7 = __shfl_sync(0xffffffffu, idx, base + k + 7);
            float4 x0 = GATHER(s0), x1 = GATHER(s1), x2 = GATHER(s2), x3 = GATHER(s3);
            float4 x4 = GATHER(s4), x5 = GATHER(s5), x6 = GATHER(s6), x7 = GATHER(s7);
            if (LAYER && half) {
                x0 = relu_add(x0, qb); x1 = relu_add(x1, qb);
                x2 = relu_add(x2, qb); x3 = relu_add(x3, qb);
                x4 = relu_add(x4, qb); x5 = relu_add(x5, qb);
                x6 = relu_add(x6, qb); x7 = relu_add(x7, qb);
            }
            acc4(acc, x0); acc4(acc, x1); acc4(acc, x2); acc4(acc, x3);
            acc4(acc, x4); acc4(acc, x5); acc4(acc, x6); acc4(acc, x7);
        }
        for (; k < m; k++) {
            int s = __shfl_sync(0xffffffffu, idx, base + k);
            float4 x = GATHER(s);
            if (LAYER && half) x = relu_add(x, qb);
            acc4(acc, x);
        }
        pr = prn;
    }
#undef GATHER

    float inv = 1.f / fmaxf((float)(e - b), 1.f);
    *(float4*)(g_hneigh + (size_t)w * 128 + half * 64 + c) =
        make_float4(acc.x * inv, acc.y * inv, acc.z * inv, acc.w * inv);
}

// ------- fused node apply + edge-weight halves: pipelined tiled GEMM --------
// (unchanged from the 324.7us best — at its instruction-mix floor)
__global__ __launch_bounds__(256) void k_apply_pq(const float* __restrict__ hn,
                                                  const float* __restrict__ wa,
                                                  const float* __restrict__ ba,
                                                  const float* __restrict__ we,
                                                  float* __restrict__ out,
                                                  float* __restrict__ P,
                                                  float* __restrict__ Q) {
    extern __shared__ __align__(16) float sm[];
    float* s_xb = sm;                      // 2 x 16 x 128 floats (16 KB), swizzled
    float* s_wb = sm + 4096;               // 2 x 16 x 64  floats (8 KB)
    float* s_y  = sm + 4096 + 2048;        // 64 x 128 floats     (32 KB)

    const int tid = threadIdx.x;
    const int cg = tid >> 5;               // warp id == column group 0..7
    const int lane = tid & 31;             // node group (4 nodes each)
    const int n0 = blockIdx.x * 128;
    const int sn = tid >> 2;               // staging node 0..63 (+64 for it=1)
    const int sf4 = tid & 3;               // staging float4 slot (== row>>2)

    const float4 f4z = make_float4(0.f, 0.f, 0.f, 0.f);
    const int swz = sf4 * 8;               // store-side XOR swizzle

    float4 xr0, xr1, wr4;
#define LOAD_X(ck)                                                             \
    do {                                                                       \
        int gn0 = n0 + sn, gn1 = n0 + sn + 64;                                 \
        xr0 = f4z; xr1 = f4z;                                                  \
        if ((ck) < 4) {                                                        \
            if (gn0 < NN) xr0 = *(const float4*)(hn + (size_t)gn0 * 64 + (ck) * 16 + sf4 * 4); \
            if (gn1 < NN) xr1 = *(const float4*)(hn + (size_t)gn1 * 64 + (ck) * 16 + sf4 * 4); \
        } else {                                                               \
            if (gn0 < NN) xr0 = *(const float4*)(g_hneigh + (size_t)gn0 * 128 + ((ck) - 4) * 16 + sf4 * 4); \
            if (gn1 < NN) xr1 = *(const float4*)(g_hneigh + (size_t)gn1 * 128 + ((ck) - 4) * 16 + sf4 * 4); \
        }                                                                      \
    } while (0)
#define STS_X(buf)                                                             \
    do {                                                                       \
        float* xb = s_xb + (buf) * 2048;                                       \
        int c0 = sn ^ swz, c1 = (sn + 64) ^ swz;                               \
        xb[(sf4 * 4 + 0) * 128 + c0] = xr0.x;                                  \
        xb[(sf4 * 4 + 1) * 128 + c0] = xr0.y;                                  \
        xb[(sf4 * 4 + 2) * 128 + c0] = xr0.z;                                  \
        xb[(sf4 * 4 + 3) * 128 + c0] = xr0.w;                                  \
        xb[(sf4 * 4 + 0) * 128 + c1] = xr1.x;                                  \
        xb[(sf4 * 4 + 1) * 128 + c1] = xr1.y;                                  \
        xb[(sf4 * 4 + 2) * 128 + c1] = xr1.z;                                  \
        xb[(sf4 * 4 + 3) * 128 + c1] = xr1.w;                                  \
    } while (0)
#define LOAD_W(base_ptr, ck) wr4 = *(const float4*)((base_ptr) + (ck) * 1024 + tid * 4)
#define STS_W(buf) *(float4*)(s_wb + (buf) * 1024 + tid * 4) = wr4

    // ---- phase A ----
    unsigned long long acc[16];
    {
        float4 b0 = *(const float4*)(ba + cg * 8);
        float4 b1 = *(const float4*)(ba + cg * 8 + 4);
#pragma unroll
        for (int n = 0; n < 4; n++) {
            acc[n * 4 + 0] = pack2(b0.x, b0.y);
            acc[n * 4 + 1] = pack2(b0.z, b0.w);
            acc[n * 4 + 2] = pack2(b1.x, b1.y);
            acc[n * 4 + 3] = pack2(b1.z, b1.w);
        }
    }

    LOAD_X(0); LOAD_W(wa, 0);
    STS_X(0); STS_W(0);
    __syncthreads();

#pragma unroll 1
    for (int ck = 0; ck < 12; ck++) {
        const int cur = ck & 1;
        const bool more = ck < 11;
        if (more) { LOAD_X(ck + 1); LOAD_W(wa, ck + 1); }
        const float* xb = s_xb + cur * 2048;
        const float* wb = s_wb + cur * 1024;
#pragma unroll
        for (int k = 0; k < 16; k++) {
            float4 xv = *(const float4*)(xb + k * 128 + ((lane * 4) ^ ((k >> 2) * 8)));
            const ulonglong2* wr = (const ulonglong2*)(wb + k * 64 + cg * 8);
            ulonglong2 wA = wr[0], wB = wr[1];
            tile_fma(acc, xv, wA, wB);
        }
        if (more) { STS_X(cur ^ 1); STS_W(cur ^ 1); __syncthreads(); }
    }

    // ---- relu, write Y, stash Y^T ----
    float y[4][8];
#pragma unroll
    for (int n = 0; n < 4; n++)
#pragma unroll
        for (int cp = 0; cp < 4; cp++) {
            float2 f = unpack2(acc[n * 4 + cp]);
            y[n][cp * 2]     = fmaxf(f.x, 0.f);
            y[n][cp * 2 + 1] = fmaxf(f.y, 0.f);
        }
#pragma unroll
    for (int n = 0; n < 4; n++) {
        int gn = n0 + lane * 4 + n;
        if (gn < NN) {
            *(float4*)(out + (size_t)gn * 64 + cg * 8) =
                make_float4(y[n][0], y[n][1], y[n][2], y[n][3]);
            *(float4*)(out + (size_t)gn * 64 + cg * 8 + 4) =
                make_float4(y[n][4], y[n][5], y[n][6], y[n][7]);
        }
    }
#pragma unroll
    for (int c = 0; c < 8; c++)
        *(float4*)(s_y + (cg * 8 + c) * 128 + lane * 4) =
            make_float4(y[0][c], y[1][c], y[2][c], y[3][c]);

    LOAD_W(we, 0);
    STS_W(0);
    __syncthreads();

    // ---- phase B ----
    unsigned long long pa[16];
#pragma unroll
    for (int i = 0; i < 16; i++) pa[i] = 0ull;

#pragma unroll 1
    for (int cc = 0; cc < 8; cc++) {
        const int cur = cc & 1;
        const bool more = cc < 7;
        if (more) LOAD_W(we, cc + 1);
        const float* wb = s_wb + cur * 1024;
        const float* yb = s_y + ((cc & 3) * 16) * 128;
#pragma unroll
        for (int k = 0; k < 16; k++) {
            float4 xv = *(const float4*)(yb + k * 128 + lane * 4);
            const ulonglong2* wr = (const ulonglong2*)(wb + k * 64 + cg * 8);
            ulonglong2 wA = wr[0], wB = wr[1];
            tile_fma(pa, xv, wA, wB);
        }
        if (cc == 3) {
#pragma unroll
            for (int n = 0; n < 4; n++) {
                int gn = n0 + lane * 4 + n;
                if (gn < NN) {
                    float2 f0 = unpack2(pa[n * 4 + 0]);
                    float2 f1 = unpack2(pa[n * 4 + 1]);
                    float2 f2 = unpack2(pa[n * 4 + 2]);
                    float2 f3 = unpack2(pa[n * 4 + 3]);
                    *(float4*)(P + (size_t)gn * 64 + cg * 8) =
                        make_float4(f0.x, f0.y, f1.x, f1.y);
                    *(float4*)(P + (size_t)gn * 64 + cg * 8 + 4) =
                        make_float4(f2.x, f2.y, f3.x, f3.y);
                }
            }
#pragma unroll
            for (int i = 0; i < 16; i++) pa[i] = 0ull;
        }
        if (more) { STS_W(cur ^ 1); __syncthreads(); }
    }
#pragma unroll
    for (int n = 0; n < 4; n++) {
        int gn = n0 + lane * 4 + n;
        if (gn < NN) {
            float2 f0 = unpack2(pa[n * 4 + 0]);
            float2 f1 = unpack2(pa[n * 4 + 1]);
            float2 f2 = unpack2(pa[n * 4 + 2]);
            float2 f3 = unpack2(pa[n * 4 + 3]);
            *(float4*)(Q + (size_t)gn * 64 + cg * 8) =
                make_float4(f0.x, f0.y, f1.x, f1.y);
            *(float4*)(Q + (size_t)gn * 64 + cg * 8 + 4) =
                make_float4(f2.x, f2.y, f3.x, f3.y);
        }
    }
#undef LOAD_X
#undef STS_X
#undef LOAD_W
#undef STS_W
}

// -------- final edge output, dst-grouped (unchanged) -------------------------
__global__ __launch_bounds__(256) void k_edge(const float* __restrict__ P,
                                              const float* __restrict__ Q,
                                              const float* __restrict__ be,
                                              float* __restrict__ oute) {
    int gtid = blockIdx.x * 256 + threadIdx.x;
    if (gtid < NN) g_cnt[gtid] = 0;
    int w = gtid >> 5;
    if (w >= NN) return;
    const int lane = threadIdx.x & 31;
    const int half = lane >> 4;
    const int c = (lane & 15) << 2;
    const int b = g_rowptr[w];
    const int e = g_rowptr[w + 1];

    float4 qb;
    {
        float4 q  = __ldg((const float4*)(Q + (size_t)w * 64 + c));
        float4 bb = *(const float4*)(be + c);
        qb = make_float4(q.x + bb.x, q.y + bb.y, q.z + bb.z, q.w + bb.w);
    }

#define PROW(s) __ldg((const float4*)(P + (size_t)(s) * 64 + c))
    int j = b + half;
    for (; j + 6 < e; j += 8) {
        int2 p0 = __ldg(g_pair + j);
        int2 p1 = __ldg(g_pair + j + 2);
        int2 p2 = __ldg(g_pair + j + 4);
        int2 p3 = __ldg(g_pair + j + 6);
        float4 r0 = PROW(p0.x), r1 = PROW(p1.x), r2 = PROW(p2.x), r3 = PROW(p3.x);
        __stcs((float4*)(oute + (size_t)p0.y * 64 + c), relu_add(r0, qb));
        __stcs((float4*)(oute + (size_t)p1.y * 64 + c), relu_add(r1, qb));
        __stcs((float4*)(oute + (size_t)p2.y * 64 + c), relu_add(r2, qb));
        __stcs((float4*)(oute + (size_t)p3.y * 64 + c), relu_add(r3, qb));
    }
    for (; j < e; j += 2) {
        int2 pp = __ldg(g_pair + j);
        float4 p = PROW(pp.x);
        __stcs((float4*)(oute + (size_t)pp.y * 64 + c), relu_add(p, qb));
    }
#undef PROW
}

// ---------------- launch ----------------
extern "C" void kernel_launch(void* const* d_in, const int* in_sizes, int n_in,
                              void* d_out, int out_size) {
    const float* nf  = (const float*)d_in[0];
    const float* ef  = (const float*)d_in[1];
    const int*   src = (const int*)d_in[2];
    const int*   dst = (const int*)d_in[3];
    const float* wa0 = (const float*)d_in[4];
    const float* ba0 = (const float*)d_in[5];
    const float* we0 = (const float*)d_in[6];
    const float* be0 = (const float*)d_in[7];
    const float* wa1 = (const float*)d_in[8];
    const float* ba1 = (const float*)d_in[9];
    const float* we1 = (const float*)d_in[10];
    const float* be1 = (const float*)d_in[11];

    float* out_n = (float*)d_out;                       // [NN, 64]
    float* out_e = out_n + (size_t)NN * DD;             // [NE, 64]

    float *hn1, *P, *Q;
    cudaGetSymbolAddress((void**)&hn1, g_hn1);
    cudaGetSymbolAddress((void**)&P, g_P);
    cudaGetSymbolAddress((void**)&Q, g_Q);

    const int APQ_SMEM = (2 * 16 * 128 + 2 * 16 * 64 + 64 * 128) * 4;  // 56 KB
    cudaFuncSetAttribute(k_apply_pq,
                         cudaFuncAttributeMaxDynamicSharedMemorySize, APQ_SMEM);

    // CSR build: single persistent kernel (count+rank -> scan -> fill)
    k_csr<<<CSR_GRID, 256>>>(src, dst);

    // layer 1
    k_agg<0><<<(NN + 7) / 8, 256>>>(nf, ef, nullptr, nullptr, nullptr);
    k_apply_pq<<<(NN + 127) / 128, 256, APQ_SMEM>>>(nf, wa0, ba0, we0, hn1, P, Q);

    // layer 2 (h_e1 never materialized: recomputed inside k_agg)   [4th launch
    // -> lands in the pinned ncu slot this round]
    k_agg<1><<<(NN + 7) / 8, 256>>>(hn1, nullptr, P, Q, be0);
    k_apply_pq<<<(NN + 127) / 128, 256, APQ_SMEM>>>(hn1, wa1, ba1, we1, out_n, P, Q);

    // final edge features, dst-grouped (+ re-zero counters)
    k_edge<<<(NN + 7) / 8, 256>>>(P, Q, be1, out_e);
}

// round 15
// speedup vs baseline: 1.0536x; 1.0536x over previous
#include <cuda_runtime.h>
#include <cstdint>

#define NN 50000
#define NE 800000
#define DD 64

// ---------------- device scratch (no allocation allowed) ----------------
// g_cnt / g_done are zero at module load and restored to zero by the end of
// every kernel_launch call.
__device__ int   g_cnt[NN];
__device__ int   g_done;
__device__ int   g_rowptr[NN + 1];
__device__ int   g_rank[NE];      // per-edge rank within its dst group
__device__ int2  g_pair[NE];      // {src node id, original edge id}, dst-grouped
__device__ float g_hneigh[(size_t)NN * 128];
__device__ float g_hn1[(size_t)NN * DD];
__device__ float g_P[(size_t)NN * DD];
__device__ float g_Q[(size_t)NN * DD];

// ---------------- f32x2 packed-FMA helpers (sm_100+) ----------------
static __device__ __forceinline__ unsigned long long pack2(float a, float b) {
    unsigned long long r;
    asm("mov.b64 %0, {%1, %2};" : "=l"(r) : "f"(a), "f"(b));
    return r;
}
static __device__ __forceinline__ float2 unpack2(unsigned long long v) {
    float2 f;
    asm("mov.b64 {%0, %1}, %2;" : "=f"(f.x), "=f"(f.y) : "l"(v));
    return f;
}
static __device__ __forceinline__ void fma2(unsigned long long& d,
                                            unsigned long long a,
                                            unsigned long long b) {
    asm("fma.rn.f32x2 %0, %1, %2, %0;" : "+l"(d) : "l"(a), "l"(b));
}

static __device__ __forceinline__ float4 relu_add(float4 x, float4 q) {
    return make_float4(fmaxf(x.x + q.x, 0.f), fmaxf(x.y + q.y, 0.f),
                       fmaxf(x.z + q.z, 0.f), fmaxf(x.w + q.w, 0.f));
}
static __device__ __forceinline__ void acc4(float4& a, float4 x) {
    a.x += x.x; a.y += x.y; a.z += x.z; a.w += x.w;
}

// 16 independent f32x2 rank-1 updates: 4 nodes x 8 cols
static __device__ __forceinline__ void tile_fma(unsigned long long* acc,
                                                float4 xv,
                                                ulonglong2 wA, ulonglong2 wB) {
    unsigned long long x0 = pack2(xv.x, xv.x), x1 = pack2(xv.y, xv.y),
                       x2 = pack2(xv.z, xv.z), x3 = pack2(xv.w, xv.w);
    fma2(acc[0],  x0, wA.x); fma2(acc[1],  x0, wA.y);
    fma2(acc[2],  x0, wB.x); fma2(acc[3],  x0, wB.y);
    fma2(acc[4],  x1, wA.x); fma2(acc[5],  x1, wA.y);
    fma2(acc[6],  x1, wB.x); fma2(acc[7],  x1, wB.y);
    fma2(acc[8],  x2, wA.x); fma2(acc[9],  x2, wA.y);
    fma2(acc[10], x2, wB.x); fma2(acc[11], x2, wB.y);
    fma2(acc[12], x3, wA.x); fma2(acc[13], x3, wA.y);
    fma2(acc[14], x3, wB.x); fma2(acc[15], x3, wB.y);
}

// -------- fused CSR count + exclusive scan (last-block-done pattern) --------
// Also records each edge's rank within its dst group so k_fill is atomic-free.
__global__ __launch_bounds__(256) void k_count_scan(const int* __restrict__ dst) {
    const int tid = threadIdx.x;
    int i = blockIdx.x * 256 + tid;
    if (i * 4 < NE) {
        int4 d4 = __ldg((const int4*)dst + i);
        int4 r4;
        r4.x = atomicAdd(&g_cnt[d4.x], 1);
        r4.y = atomicAdd(&g_cnt[d4.y], 1);
        r4.z = atomicAdd(&g_cnt[d4.z], 1);
        r4.w = atomicAdd(&g_cnt[d4.w], 1);
        ((int4*)g_rank)[i] = r4;
    }
    __threadfence();
    __syncthreads();

    __shared__ int s_last;
    if (tid == 0) s_last = (atomicAdd(&g_done, 1) == (int)gridDim.x - 1);
    __syncthreads();
    if (!s_last) return;

    __threadfence();
    if (tid == 0) g_done = 0;

    __shared__ int part[256];
    const int C = (NN + 255) / 256;
    int beg = tid * C;
    int end = min(beg + C, NN);
    int s = 0;
    for (int j = beg; j < end; j++) s += g_cnt[j];
    part[tid] = s;
    __syncthreads();
    for (int off = 1; off < 256; off <<= 1) {
        int add = (tid >= off) ? part[tid - off] : 0;
        __syncthreads();
        part[tid] += add;
        __syncthreads();
    }
    int run = (tid == 0) ? 0 : part[tid - 1];
    for (int j = beg; j < end; j++) { g_rowptr[j] = run; run += g_cnt[j]; }
    if (tid == 255) g_rowptr[NN] = part[255];
}

// atomic-free fill: position = rowptr[dst] + rank (precomputed in count pass)
__global__ void k_fill(const int* __restrict__ src, const int* __restrict__ dst) {
    int i = blockIdx.x * blockDim.x + threadIdx.x;
    if (i * 4 >= NE) return;
    int4 d4 = __ldg((const int4*)dst + i);
    int4 s4 = __ldg((const int4*)src + i);
    int4 r4 = __ldg((const int4*)g_rank + i);
    int e = i * 4;
    g_pair[__ldg(g_rowptr + d4.x) + r4.x] = make_int2(s4.x, e);
    g_pair[__ldg(g_rowptr + d4.y) + r4.y] = make_int2(s4.y, e + 1);
    g_pair[__ldg(g_rowptr + d4.z) + r4.z] = make_int2(s4.z, e + 2);
    g_pair[__ldg(g_rowptr + d4.w) + r4.w] = make_int2(s4.w, e + 3);
}

// ---------------- aggregation: one warp per node, mean of [h[src] | h_e] ----
// Full 16-edge windows use a 16-deep batched gather (double the in-flight
// loads of the previous 8-deep path) to cover DRAM latency on the efeats
// stream; partial windows fall back to the scalar loop.
template <int LAYER>
static __device__ __forceinline__ float4 gat(const float* __restrict__ tb,
                                             int s, int c, int half) {
    const float4* p = (const float4*)(tb + (size_t)s * 64 + c);
    if (LAYER == 0) return half ? __ldcs(p) : __ldg(p);
    return __ldg(p);
}

template <int LAYER>
__global__ __launch_bounds__(256) void k_agg(const float* __restrict__ hn,
                                             const float* __restrict__ ef,
                                             const float* __restrict__ P0,
                                             const float* __restrict__ Q0,
                                             const float* __restrict__ be0) {
    int w = (blockIdx.x * 256 + threadIdx.x) >> 5;
    if (w >= NN) return;
    const int lane = threadIdx.x & 31;
    const int half = lane >> 4;
    const int t = lane & 15;
    const int c = t << 2;
    const int base = half << 4;
    const int b = g_rowptr[w];
    const int e = g_rowptr[w + 1];

    const float* tb = half ? (LAYER ? P0 : ef) : hn;

    float4 qb = make_float4(0.f, 0.f, 0.f, 0.f);
    if (LAYER && half) {
        float4 q  = *(const float4*)(Q0 + (size_t)w * 64 + c);
        float4 bb = *(const float4*)(be0 + c);
        qb = make_float4(q.x + bb.x, q.y + bb.y, q.z + bb.z, q.w + bb.w);
    }

    float4 acc = make_float4(0.f, 0.f, 0.f, 0.f);

    int2 pr = make_int2(0, 0);
    if (b + t < e) pr = __ldg(g_pair + b + t);

#define GATHER(s) gat<LAYER>(tb, (s), c, half)
    for (int j0 = b; j0 < e; j0 += 16) {
        int m = e - j0;
        if (m > 16) m = 16;
        int idx = (LAYER == 0 && half) ? pr.y : pr.x;
        int2 prn = make_int2(0, 0);
        int j1 = j0 + 16;
        if (j1 + t < e) prn = __ldg(g_pair + j1 + t);

        if (m == 16) {
            // fast path: all 16 gathers in flight before any accumulation
            int s[16];
#pragma unroll
            for (int k = 0; k < 16; k++)
                s[k] = __shfl_sync(0xffffffffu, idx, base + k);
            float4 x[16];
#pragma unroll
            for (int k = 0; k < 16; k++) x[k] = GATHER(s[k]);
#pragma unroll
            for (int k = 0; k < 16; k++) {
                if (LAYER && half) x[k] = relu_add(x[k], qb);
                acc4(acc, x[k]);
            }
        } else {
            int k = 0;
            for (; k + 4 <= m; k += 4) {
                int s0 = __shfl_sync(0xffffffffu, idx, base + k);
                int s1 = __shfl_sync(0xffffffffu, idx, base + k + 1);
                int s2 = __shfl_sync(0xffffffffu, idx, base + k + 2);
                int s3 = __shfl_sync(0xffffffffu, idx, base + k + 3);
                float4 x0 = GATHER(s0), x1 = GATHER(s1);
                float4 x2 = GATHER(s2), x3 = GATHER(s3);
                if (LAYER && half) {
                    x0 = relu_add(x0, qb); x1 = relu_add(x1, qb);
                    x2 = relu_add(x2, qb); x3 = relu_add(x3, qb);
                }
                acc4(acc, x0); acc4(acc, x1); acc4(acc, x2); acc4(acc, x3);
            }
            for (; k < m; k++) {
                int s = __shfl_sync(0xffffffffu, idx, base + k);
                float4 x = GATHER(s);
                if (LAYER && half) x = relu_add(x, qb);
                acc4(acc, x);
            }
        }
        pr = prn;
    }
#undef GATHER

    float inv = 1.f / fmaxf((float)(e - b), 1.f);
    *(float4*)(g_hneigh + (size_t)w * 128 + half * 64 + c) =
        make_float4(acc.x * inv, acc.y * inv, acc.z * inv, acc.w * inv);
}

// ------- fused node apply + edge-weight halves: pipelined tiled GEMM --------
// (unchanged from the 324.7us best — at its instruction-mix floor)
__global__ __launch_bounds__(256) void k_apply_pq(const float* __restrict__ hn,
                                                  const float* __restrict__ wa,
                                                  const float* __restrict__ ba,
                                                  const float* __restrict__ we,
                                                  float* __restrict__ out,
                                                  float* __restrict__ P,
                                                  float* __restrict__ Q) {
    extern __shared__ __align__(16) float sm[];
    float* s_xb = sm;                      // 2 x 16 x 128 floats (16 KB), swizzled
    float* s_wb = sm + 4096;               // 2 x 16 x 64  floats (8 KB)
    float* s_y  = sm + 4096 + 2048;        // 64 x 128 floats     (32 KB)

    const int tid = threadIdx.x;
    const int cg = tid >> 5;               // warp id == column group 0..7
    const int lane = tid & 31;             // node group (4 nodes each)
    const int n0 = blockIdx.x * 128;
    const int sn = tid >> 2;               // staging node 0..63 (+64 for it=1)
    const int sf4 = tid & 3;               // staging float4 slot (== row>>2)

    const float4 f4z = make_float4(0.f, 0.f, 0.f, 0.f);
    const int swz = sf4 * 8;               // store-side XOR swizzle

    float4 xr0, xr1, wr4;
#define LOAD_X(ck)                                                             \
    do {                                                                       \
        int gn0 = n0 + sn, gn1 = n0 + sn + 64;                                 \
        xr0 = f4z; xr1 = f4z;                                                  \
        if ((ck) < 4) {                                                        \
            if (gn0 < NN) xr0 = *(const float4*)(hn + (size_t)gn0 * 64 + (ck) * 16 + sf4 * 4); \
            if (gn1 < NN) xr1 = *(const float4*)(hn + (size_t)gn1 * 64 + (ck) * 16 + sf4 * 4); \
        } else {                                                               \
            if (gn0 < NN) xr0 = *(const float4*)(g_hneigh + (size_t)gn0 * 128 + ((ck) - 4) * 16 + sf4 * 4); \
            if (gn1 < NN) xr1 = *(const float4*)(g_hneigh + (size_t)gn1 * 128 + ((ck) - 4) * 16 + sf4 * 4); \
        }                                                                      \
    } while (0)
#define STS_X(buf)                                                             \
    do {                                                                       \
        float* xb = s_xb + (buf) * 2048;                                       \
        int c0 = sn ^ swz, c1 = (sn + 64) ^ swz;                               \
        xb[(sf4 * 4 + 0) * 128 + c0] = xr0.x;                                  \
        xb[(sf4 * 4 + 1) * 128 + c0] = xr0.y;                                  \
        xb[(sf4 * 4 + 2) * 128 + c0] = xr0.z;                                  \
        xb[(sf4 * 4 + 3) * 128 + c0] = xr0.w;                                  \
        xb[(sf4 * 4 + 0) * 128 + c1] = xr1.x;                                  \
        xb[(sf4 * 4 + 1) * 128 + c1] = xr1.y;                                  \
        xb[(sf4 * 4 + 2) * 128 + c1] = xr1.z;                                  \
        xb[(sf4 * 4 + 3) * 128 + c1] = xr1.w;                                  \
    } while (0)
#define LOAD_W(base_ptr, ck) wr4 = *(const float4*)((base_ptr) + (ck) * 1024 + tid * 4)
#define STS_W(buf) *(float4*)(s_wb + (buf) * 1024 + tid * 4) = wr4

    // ---- phase A ----
    unsigned long long acc[16];
    {
        float4 b0 = *(const float4*)(ba + cg * 8);
        float4 b1 = *(const float4*)(ba + cg * 8 + 4);
#pragma unroll
        for (int n = 0; n < 4; n++) {
            acc[n * 4 + 0] = pack2(b0.x, b0.y);
            acc[n * 4 + 1] = pack2(b0.z, b0.w);
            acc[n * 4 + 2] = pack2(b1.x, b1.y);
            acc[n * 4 + 3] = pack2(b1.z, b1.w);
        }
    }

    LOAD_X(0); LOAD_W(wa, 0);
    STS_X(0); STS_W(0);
    __syncthreads();

#pragma unroll 1
    for (int ck = 0; ck < 12; ck++) {
        const int cur = ck & 1;
        const bool more = ck < 11;
        if (more) { LOAD_X(ck + 1); LOAD_W(wa, ck + 1); }
        const float* xb = s_xb + cur * 2048;
        const float* wb = s_wb + cur * 1024;
#pragma unroll
        for (int k = 0; k < 16; k++) {
            float4 xv = *(const float4*)(xb + k * 128 + ((lane * 4) ^ ((k >> 2) * 8)));
            const ulonglong2* wr = (const ulonglong2*)(wb + k * 64 + cg * 8);
            ulonglong2 wA = wr[0], wB = wr[1];
            tile_fma(acc, xv, wA, wB);
        }
        if (more) { STS_X(cur ^ 1); STS_W(cur ^ 1); __syncthreads(); }
    }

    // ---- relu, write Y, stash Y^T ----
    float y[4][8];
#pragma unroll
    for (int n = 0; n < 4; n++)
#pragma unroll
        for (int cp = 0; cp < 4; cp++) {
            float2 f = unpack2(acc[n * 4 + cp]);
            y[n][cp * 2]     = fmaxf(f.x, 0.f);
            y[n][cp * 2 + 1] = fmaxf(f.y, 0.f);
        }
#pragma unroll
    for (int n = 0; n < 4; n++) {
        int gn = n0 + lane * 4 + n;
        if (gn < NN) {
            *(float4*)(out + (size_t)gn * 64 + cg * 8) =
                make_float4(y[n][0], y[n][1], y[n][2], y[n][3]);
            *(float4*)(out + (size_t)gn * 64 + cg * 8 + 4) =
                make_float4(y[n][4], y[n][5], y[n][6], y[n][7]);
        }
    }
#pragma unroll
    for (int c = 0; c < 8; c++)
        *(float4*)(s_y + (cg * 8 + c) * 128 + lane * 4) =
            make_float4(y[0][c], y[1][c], y[2][c], y[3][c]);

    LOAD_W(we, 0);
    STS_W(0);
    __syncthreads();

    // ---- phase B ----
    unsigned long long pa[16];
#pragma unroll
    for (int i = 0; i < 16; i++) pa[i] = 0ull;

#pragma unroll 1
    for (int cc = 0; cc < 8; cc++) {
        const int cur = cc & 1;
        const bool more = cc < 7;
        if (more) LOAD_W(we, cc + 1);
        const float* wb = s_wb + cur * 1024;
        const float* yb = s_y + ((cc & 3) * 16) * 128;
#pragma unroll
        for (int k = 0; k < 16; k++) {
            float4 xv = *(const float4*)(yb + k * 128 + lane * 4);
            const ulonglong2* wr = (const ulonglong2*)(wb + k * 64 + cg * 8);
            ulonglong2 wA = wr[0], wB = wr[1];
            tile_fma(pa, xv, wA, wB);
        }
        if (cc == 3) {
#pragma unroll
            for (int n = 0; n < 4; n++) {
                int gn = n0 + lane * 4 + n;
                if (gn < NN) {
                    float2 f0 = unpack2(pa[n * 4 + 0]);
                    float2 f1 = unpack2(pa[n * 4 + 1]);
                    float2 f2 = unpack2(pa[n * 4 + 2]);
                    float2 f3 = unpack2(pa[n * 4 + 3]);
                    *(float4*)(P + (size_t)gn * 64 + cg * 8) =
                        make_float4(f0.x, f0.y, f1.x, f1.y);
                    *(float4*)(P + (size_t)gn * 64 + cg * 8 + 4) =
                        make_float4(f2.x, f2.y, f3.x, f3.y);
                }
            }
#pragma unroll
            for (int i = 0; i < 16; i++) pa[i] = 0ull;
        }
        if (more) { STS_W(cur ^ 1); __syncthreads(); }
    }
#pragma unroll
    for (int n = 0; n < 4; n++) {
        int gn = n0 + lane * 4 + n;
        if (gn < NN) {
            float2 f0 = unpack2(pa[n * 4 + 0]);
            float2 f1 = unpack2(pa[n * 4 + 1]);
            float2 f2 = unpack2(pa[n * 4 + 2]);
            float2 f3 = unpack2(pa[n * 4 + 3]);
            *(float4*)(Q + (size_t)gn * 64 + cg * 8) =
                make_float4(f0.x, f0.y, f1.x, f1.y);
            *(float4*)(Q + (size_t)gn * 64 + cg * 8 + 4) =
                make_float4(f2.x, f2.y, f3.x, f3.y);
        }
    }
#undef LOAD_X
#undef STS_X
#undef LOAD_W
#undef STS_W
}

// -------- final edge output, dst-grouped (unchanged) -------------------------
__global__ __launch_bounds__(256) void k_edge(const float* __restrict__ P,
                                              const float* __restrict__ Q,
                                              const float* __restrict__ be,
                                              float* __restrict__ oute) {
    int gtid = blockIdx.x * 256 + threadIdx.x;
    if (gtid < NN) g_cnt[gtid] = 0;
    int w = gtid >> 5;
    if (w >= NN) return;
    const int lane = threadIdx.x & 31;
    const int half = lane >> 4;
    const int c = (lane & 15) << 2;
    const int b = g_rowptr[w];
    const int e = g_rowptr[w + 1];

    float4 qb;
    {
        float4 q  = __ldg((const float4*)(Q + (size_t)w * 64 + c));
        float4 bb = *(const float4*)(be + c);
        qb = make_float4(q.x + bb.x, q.y + bb.y, q.z + bb.z, q.w + bb.w);
    }

#define PROW(s) __ldg((const float4*)(P + (size_t)(s) * 64 + c))
    int j = b + half;
    for (; j + 6 < e; j += 8) {
        int2 p0 = __ldg(g_pair + j);
        int2 p1 = __ldg(g_pair + j + 2);
        int2 p2 = __ldg(g_pair + j + 4);
        int2 p3 = __ldg(g_pair + j + 6);
        float4 r0 = PROW(p0.x), r1 = PROW(p1.x), r2 = PROW(p2.x), r3 = PROW(p3.x);
        __stcs((float4*)(oute + (size_t)p0.y * 64 + c), relu_add(r0, qb));
        __stcs((float4*)(oute + (size_t)p1.y * 64 + c), relu_add(r1, qb));
        __stcs((float4*)(oute + (size_t)p2.y * 64 + c), relu_add(r2, qb));
        __stcs((float4*)(oute + (size_t)p3.y * 64 + c), relu_add(r3, qb));
    }
    for (; j < e; j += 2) {
        int2 pp = __ldg(g_pair + j);
        float4 p = PROW(pp.x);
        __stcs((float4*)(oute + (size_t)pp.y * 64 + c), relu_add(p, qb));
    }
#undef PROW
}

// ---------------- launch ----------------
extern "C" void kernel_launch(void* const* d_in, const int* in_sizes, int n_in,
                              void* d_out, int out_size) {
    const float* nf  = (const float*)d_in[0];
    const float* ef  = (const float*)d_in[1];
    const int*   src = (const int*)d_in[2];
    const int*   dst = (const int*)d_in[3];
    const float* wa0 = (const float*)d_in[4];
    const float* ba0 = (const float*)d_in[5];
    const float* we0 = (const float*)d_in[6];
    const float* be0 = (const float*)d_in[7];
    const float* wa1 = (const float*)d_in[8];
    const float* ba1 = (const float*)d_in[9];
    const float* we1 = (const float*)d_in[10];
    const float* be1 = (const float*)d_in[11];

    float* out_n = (float*)d_out;                       // [NN, 64]
    float* out_e = out_n + (size_t)NN * DD;             // [NE, 64]

    float *hn1, *P, *Q;
    cudaGetSymbolAddress((void**)&hn1, g_hn1);
    cudaGetSymbolAddress((void**)&P, g_P);
    cudaGetSymbolAddress((void**)&Q, g_Q);

    const int APQ_SMEM = (2 * 16 * 128 + 2 * 16 * 64 + 64 * 128) * 4;  // 56 KB
    cudaFuncSetAttribute(k_apply_pq,
                         cudaFuncAttributeMaxDynamicSharedMemorySize, APQ_SMEM);

    // CSR build (two small kernels — measured faster than the persistent fuse)
    k_count_scan<<<(NE / 4 + 255) / 256, 256>>>(dst);
    k_fill<<<(NE / 4 + 255) / 256, 256>>>(src, dst);

    // layer 1
    k_agg<0><<<(NN + 7) / 8, 256>>>(nf, ef, nullptr, nullptr, nullptr);
    k_apply_pq<<<(NN + 127) / 128, 256, APQ_SMEM>>>(nf, wa0, ba0, we0, hn1, P, Q);

    // layer 2 (h_e1 never materialized: recomputed inside k_agg)
    k_agg<1><<<(NN + 7) / 8, 256>>>(hn1, nullptr, P, Q, be0);
    k_apply_pq<<<(NN + 127) / 128, 256, APQ_SMEM>>>(hn1, wa1, ba1, we1, out_n, P, Q);

    // final edge features, dst-grouped (+ re-zero counters)
    k_edge<<<(NN + 7) / 8, 256>>>(P, Q, be1, out_e);
}